// round 13
// baseline (speedup 1.0000x reference)
#include <cuda_runtime.h>
#include <cuda_bf16.h>
#include <math.h>
#include <stdint.h>

#define C_CH   128
#define N_PTS  32768
#define K_PWL  20
#define LATENT 8
#define HID    8
#define NSEG   (K_PWL - 1)

// ---------------- scratch (static device memory; no allocations) ----------------
__device__ float g_x[(size_t)C_CH * N_PTS];     // raw x MLP outputs [C][N]
__device__ float g_e[(size_t)C_CH * N_PTS];     // raw e MLP outputs [C][N]
__device__ float g_slope[C_CH * NSEG];          // per-channel PWL segment slopes
__device__ float g_icept[C_CH * NSEG];          // per-channel PWL segment intercepts
__device__ unsigned int g_minbits[C_CH];
__device__ unsigned int g_maxbits[C_CH];
__device__ float g_minv[C_CH];
__device__ float g_scale[C_CH];
__device__ float g_psum[2048];
__device__ float g_psumsq[2048];
__device__ float g_eA;   // 0.1 * invstd
__device__ float g_eB;   // -0.1 * mean * invstd
__device__ unsigned int g_done;  // zero-init; reset by finalize each run

// xp = linspace(0,1,20) in f32
#define XPV(k) ((float)((double)(k) / 19.0))
__constant__ float c_xp[K_PWL] = {
    XPV(0), XPV(1), XPV(2), XPV(3), XPV(4), XPV(5), XPV(6), XPV(7), XPV(8), XPV(9),
    XPV(10), XPV(11), XPV(12), XPV(13), XPV(14), XPV(15), XPV(16), XPV(17), XPV(18), XPV(19)
};

// ---------------- helpers ----------------
__device__ __forceinline__ unsigned int fenc(float f) {
    unsigned int u = __float_as_uint(f);
    return (u >> 31) ? ~u : (u | 0x80000000u);
}
__device__ __forceinline__ float fdec(unsigned int u) {
    return (u & 0x80000000u) ? __uint_as_float(u & 0x7FFFFFFFu) : __uint_as_float(~u);
}

// Clamped fast tanh (gen kernel only; not perf-critical).
__device__ __forceinline__ float tanh_fast(float x) {
    x = fminf(fmaxf(x, -30.0f), 30.0f);
    float t = __expf(2.0f * x);
    return __fdividef(t - 1.0f, t + 1.0f);
}

// Lean 5-instruction tanh for the pass kernels: t = 2^(x*2*log2 e);
// (t-1)/(t+1) = t*r - r with r = rcp(t+1). Inputs bounded (|x| < ~20 by
// weight/activation analysis), so no clamp needed (ex2 overflows only at x>44).
__device__ __forceinline__ float tanh5(float x) {
    float t;
    asm("ex2.approx.f32 %0, %1;" : "=f"(t) : "f"(x * 2.8853900817779268f));
    float r;
    asm("rcp.approx.f32 %0, %1;" : "=f"(r) : "f"(t + 1.0f));
    return fmaf(t, r, -r);
}

// ---------------- f32x2 packed helpers (Blackwell dual-FP32) ----------------
__device__ __forceinline__ unsigned long long packf2(float lo, float hi) {
    unsigned long long r;
    asm("mov.b64 %0, {%1, %2};" : "=l"(r) : "f"(lo), "f"(hi));
    return r;
}
__device__ __forceinline__ void unpackf2(unsigned long long v, float& lo, float& hi) {
    asm("mov.b64 {%0, %1}, %2;" : "=f"(lo), "=f"(hi) : "l"(v));
}
__device__ __forceinline__ unsigned long long fma2(unsigned long long a,
                                                   unsigned long long b,
                                                   unsigned long long c) {
    unsigned long long d;
    asm("fma.rn.f32x2 %0, %1, %2, %3;" : "=l"(d) : "l"(a), "l"(b), "l"(c));
    return d;
}
__device__ __forceinline__ unsigned long long add2(unsigned long long a,
                                                   unsigned long long b) {
    unsigned long long d;
    asm("add.rn.f32x2 %0, %1, %2;" : "=l"(d) : "l"(a), "l"(b));
    return d;
}

// ---------------- shared-memory weights (duplicated f32x2 pairs) ----------------
struct PassSmem {
    unsigned long long w1d[64];  // W1[i*8+j] duplicated (w,w) — 512B, 16B aligned
    unsigned long long b1d[8];   // b1 duplicated
    float red1[256];
    float red2[256];
};

__device__ __forceinline__ void load_weights_dup(
    PassSmem& sm, int tid,
    const float* __restrict__ W1, const float* __restrict__ b1) {
    if (tid < 64) {
        unsigned int u = __float_as_uint(__ldg(W1 + tid));
        sm.w1d[tid] = ((unsigned long long)u << 32) | u;
    } else if (tid < 72) {
        unsigned int u = __float_as_uint(__ldg(b1 + tid - 64));
        sm.b1d[tid - 64] = ((unsigned long long)u << 32) | u;
    }
}

// MLP for a pair of points (p0, p1). W1/b1 from smem (dup pairs, FFMA2);
// W2/b2 from per-thread registers.
__device__ __forceinline__ void mlp_pair(
    const PassSmem& sm, const float* w2r, float b2r,
    float4 a0, float4 b0, float4 a1, float4 b1q,
    float& v0, float& v1) {
    unsigned long long zp[8];
    zp[0] = packf2(a0.x, a1.x); zp[1] = packf2(a0.y, a1.y);
    zp[2] = packf2(a0.z, a1.z); zp[3] = packf2(a0.w, a1.w);
    zp[4] = packf2(b0.x, b1q.x); zp[5] = packf2(b0.y, b1q.y);
    zp[6] = packf2(b0.z, b1q.z); zp[7] = packf2(b0.w, b1q.w);

    unsigned long long h[8];
    {
        const ulonglong2* bb = reinterpret_cast<const ulonglong2*>(sm.b1d);
#pragma unroll
        for (int jj = 0; jj < 4; jj++) { ulonglong2 p = bb[jj]; h[2 * jj] = p.x; h[2 * jj + 1] = p.y; }
    }
    const ulonglong2* wv = reinterpret_cast<const ulonglong2*>(sm.w1d);
#pragma unroll
    for (int i = 0; i < 8; i++) {
        unsigned long long z = zp[i];
#pragma unroll
        for (int jj = 0; jj < 4; jj++) {
            ulonglong2 wp = wv[i * 4 + jj];
            h[2 * jj]     = fma2(z, wp.x, h[2 * jj]);
            h[2 * jj + 1] = fma2(z, wp.y, h[2 * jj + 1]);
        }
    }
    float o0 = b2r, o1 = b2r;
#pragma unroll
    for (int j = 0; j < 8; j++) {
        float x0, x1;
        unpackf2(h[j], x0, x1);
        o0 = fmaf(tanh5(x0), w2r[j], o0);
        o1 = fmaf(tanh5(x1), w2r[j], o1);
    }
    v0 = tanh5(o0);
    v1 = tanh5(o1);
}

// ---------------- K1: PWL generator (tiny) + slope/intercept tables + init ----------------
__global__ void gen_pwl_kernel(const float* __restrict__ zf,
                               const float* __restrict__ Wf1, const float* __restrict__ bf1,
                               const float* __restrict__ Wf2, const float* __restrict__ bf2,
                               const void* __restrict__ dirs_raw) {
    int c = threadIdx.x;  // 128 threads, one per channel
    __shared__ unsigned int flags;
    if (c == 0) { flags = 0u; g_done = 0u; }
    __syncthreads();
    {
        unsigned char v = ((const unsigned char*)dirs_raw)[c];
        unsigned int f = 0u;
        if ((c & 3) != 0 && v != 0) f |= 1u;
        if (v > 1) f |= 2u;
        if (f) atomicOr(&flags, f);
    }
    __syncthreads();
    // mode: 0 = int32, 1 = uint8/bool, 2 = float32
    const int mode = (!(flags & 1u)) ? 0 : ((!(flags & 2u)) ? 1 : 2);

    float z[LATENT];
#pragma unroll
    for (int i = 0; i < LATENT; i++) z[i] = zf[c * LATENT + i];

    float h[HID];
#pragma unroll
    for (int j = 0; j < HID; j++) h[j] = bf1[j];
#pragma unroll
    for (int i = 0; i < LATENT; i++)
#pragma unroll
        for (int j = 0; j < HID; j++) h[j] = fmaf(z[i], Wf1[i * HID + j], h[j]);
#pragma unroll
    for (int j = 0; j < HID; j++) h[j] = tanh_fast(h[j]);

    float pts[K_PWL];
#pragma unroll
    for (int k = 0; k < K_PWL; k++) {
        float s = bf2[k];
#pragma unroll
        for (int j = 0; j < HID; j++) s = fmaf(h[j], Wf2[j * K_PWL + k], s);
        pts[k] = tanh_fast(s);
    }
    // insertion sort ascending
    for (int a = 1; a < K_PWL; a++) {
        float v = pts[a];
        int b = a - 1;
        while (b >= 0 && pts[b] > v) { pts[b + 1] = pts[b]; b--; }
        pts[b + 1] = v;
    }
    bool dir;
    if (mode == 0)      dir = ((const int*)dirs_raw)[c] != 0;
    else if (mode == 1) dir = ((const unsigned char*)dirs_raw)[c] != 0;
    else                dir = ((const float*)dirs_raw)[c] > 0.5f;

    for (int k = 0; k < NSEG; k++) {
        float y0 = dir ? pts[k]     : pts[K_PWL - 1 - k];
        float y1 = dir ? pts[k + 1] : pts[K_PWL - 2 - k];
        float sl = (y1 - y0) / (c_xp[k + 1] - c_xp[k] + 1e-7f);
        g_slope[c * NSEG + k] = sl;
        g_icept[c * NSEG + k] = fmaf(-c_xp[k], sl, y0);
    }

    g_minbits[c] = 0xFFFFFFFFu;
    g_maxbits[c] = 0u;
}

// ---------------- K2: x MLP (f32x2 pairs) + per-channel min/max ----------------
__global__ void __launch_bounds__(256, 4) pass_x_kernel(
    const float* __restrict__ zx,
    const float* __restrict__ W1, const float* __restrict__ b1,
    const float* __restrict__ W2, const float* __restrict__ b2) {
    __shared__ PassSmem sm;
    const int tid = threadIdx.x;
    load_weights_dup(sm, tid, W1, b1);
    float w2r[8];
#pragma unroll
    for (int j = 0; j < 8; j++) w2r[j] = __ldg(W2 + j);
    const float b2r = __ldg(b2);
    __syncthreads();

    const int c = blockIdx.y;
    const size_t base = (size_t)c * N_PTS;
    const int n0 = blockIdx.x * 2048;
    const float4* __restrict__ src4 = reinterpret_cast<const float4*>(zx + base * LATENT);

    float lmin = 1e30f, lmax = -1e30f;
#pragma unroll
    for (int k = 0; k < 4; k++) {
        int n = n0 + k * 512 + tid;
        float4 a0 = src4[2 * n],         b0  = src4[2 * n + 1];
        float4 a1 = src4[2 * (n + 256)], b1q = src4[2 * (n + 256) + 1];
        float v0, v1;
        mlp_pair(sm, w2r, b2r, a0, b0, a1, b1q, v0, v1);
        g_x[base + n] = v0;
        g_x[base + n + 256] = v1;
        lmin = fminf(lmin, fminf(v0, v1));
        lmax = fmaxf(lmax, fmaxf(v0, v1));
    }

    sm.red1[tid] = lmin; sm.red2[tid] = lmax; __syncthreads();
    for (int s = 128; s; s >>= 1) {
        if (tid < s) {
            sm.red1[tid] = fminf(sm.red1[tid], sm.red1[tid + s]);
            sm.red2[tid] = fmaxf(sm.red2[tid], sm.red2[tid + s]);
        }
        __syncthreads();
    }
    if (tid == 0) {
        atomicMin(&g_minbits[c], fenc(sm.red1[0]));
        atomicMax(&g_maxbits[c], fenc(sm.red2[0]));
    }
}

// ---------------- K3: e MLP (f32x2 pairs) + partials + last-block finalize ----------------
__global__ void __launch_bounds__(256, 4) pass_e_kernel(
    const float* __restrict__ ze,
    const float* __restrict__ W1, const float* __restrict__ b1,
    const float* __restrict__ W2, const float* __restrict__ b2) {
    __shared__ PassSmem sm;
    const int tid = threadIdx.x;
    load_weights_dup(sm, tid, W1, b1);
    float w2r[8];
#pragma unroll
    for (int j = 0; j < 8; j++) w2r[j] = __ldg(W2 + j);
    const float b2r = __ldg(b2);
    __syncthreads();

    const int c = blockIdx.y;
    const size_t base = (size_t)c * N_PTS;
    const int n0 = blockIdx.x * 2048;
    const float4* __restrict__ src4 = reinterpret_cast<const float4*>(ze + base * LATENT);

    unsigned long long lsp = packf2(0.0f, 0.0f);
    unsigned long long lqp = packf2(0.0f, 0.0f);
#pragma unroll
    for (int k = 0; k < 4; k++) {
        int n = n0 + k * 512 + tid;
        float4 a0 = src4[2 * n],         b0  = src4[2 * n + 1];
        float4 a1 = src4[2 * (n + 256)], b1q = src4[2 * (n + 256) + 1];
        float v0, v1;
        mlp_pair(sm, w2r, b2r, a0, b0, a1, b1q, v0, v1);
        g_e[base + n] = v0;
        g_e[base + n + 256] = v1;
        unsigned long long vp = packf2(v0, v1);
        lsp = add2(lsp, vp);
        lqp = fma2(vp, vp, lqp);
    }
    float s0, s1, q0, q1;
    unpackf2(lsp, s0, s1);
    unpackf2(lqp, q0, q1);
    float ls = s0 + s1, lq = q0 + q1;

    __shared__ bool amLast;
    sm.red1[tid] = ls; sm.red2[tid] = lq; __syncthreads();
    for (int s = 128; s; s >>= 1) {
        if (tid < s) { sm.red1[tid] += sm.red1[tid + s]; sm.red2[tid] += sm.red2[tid + s]; }
        __syncthreads();
    }
    if (tid == 0) {
        int pid = blockIdx.y * gridDim.x + blockIdx.x;
        g_psum[pid] = sm.red1[0];
        g_psumsq[pid] = sm.red2[0];
        __threadfence();                       // release partials
        unsigned int t = atomicAdd(&g_done, 1u);
        amLast = (t == 2048u - 1u);
    }
    __syncthreads();

    if (amLast) {
        __threadfence();                       // acquire all partials
        double s = 0.0, q = 0.0;
#pragma unroll
        for (int i = 0; i < 8; i++) {
            int idx = tid + i * 256;
            s += (double)g_psum[idx];
            q += (double)g_psumsq[idx];
        }
        double* sds = reinterpret_cast<double*>(sm.red1);  // 2KB: 256 doubles
        sds[tid] = s; __syncthreads();
        for (int k = 128; k; k >>= 1) {
            if (tid < k) sds[tid] += sds[tid + k];
            __syncthreads();
        }
        double stot = sds[0]; __syncthreads();
        sds[tid] = q; __syncthreads();
        for (int k = 128; k; k >>= 1) {
            if (tid < k) sds[tid] += sds[tid + k];
            __syncthreads();
        }
        double qtot = sds[0];
        if (tid == 0) {
            double CN = (double)C_CH * (double)N_PTS;
            double mean = stot / CN;
            double var = (qtot - stot * stot / CN) / (CN - 1.0);
            double invstd = 1.0 / sqrt(var);
            g_eA = (float)(0.1 * invstd);
            g_eB = (float)(-0.1 * mean * invstd);
            g_done = 0u;                       // reset for next graph replay
        }
        if (tid < C_CH) {
            float mn = fdec(g_minbits[tid]);
            float mx = fdec(g_maxbits[tid]);
            g_minv[tid] = mn;
            g_scale[tid] = 1.0f / (mx - mn);
        }
        __threadfence();
    }
}

// ---------------- K4: transpose + direct-index PWL + noise (double-buffered) ----------------
__global__ void __launch_bounds__(256) out_kernel(float* __restrict__ out) {
    __shared__ float sx[2][32][33];
    __shared__ float se[2][32][33];
    __shared__ float ssl[32][NSEG + 1];
    __shared__ float ssb[32][NSEG + 1];
    __shared__ float smn[32];
    __shared__ float ssc[32];

    const int tx = threadIdx.x, ty = threadIdx.y;
    const int tid = ty * 32 + tx;
    const int nb = blockIdx.x * 128;
    const int c0 = blockIdx.y * 32;

    for (int idx = tid; idx < 32 * NSEG; idx += 256) {
        int cl = idx / NSEG, k = idx % NSEG;
        ssl[cl][k] = g_slope[(c0 + cl) * NSEG + k];
        ssb[cl][k] = g_icept[(c0 + cl) * NSEG + k];
    }
    if (tid < 32) {
        smn[tid] = g_minv[c0 + tid];
        ssc[tid] = g_scale[c0 + tid];
    }
    const float eA = g_eA, eB = g_eB;

    float rx[4], re[4];
#pragma unroll
    for (int r = 0; r < 4; r++) {
        int cl = ty + r * 8;
        size_t off = (size_t)(c0 + cl) * N_PTS + nb + tx;
        rx[r] = g_x[off];
        re[r] = g_e[off];
    }
#pragma unroll
    for (int r = 0; r < 4; r++) {
        int cl = ty + r * 8;
        sx[0][cl][tx] = rx[r];
        se[0][cl][tx] = re[r];
    }
    __syncthreads();

    const float mn = smn[tx], sc = ssc[tx];

#pragma unroll
    for (int t = 0; t < 4; t++) {
        const int cur = t & 1;
        if (t < 3) {
            const int n1 = nb + (t + 1) * 32;
#pragma unroll
            for (int r = 0; r < 4; r++) {
                int cl = ty + r * 8;
                size_t off = (size_t)(c0 + cl) * N_PTS + n1 + tx;
                rx[r] = g_x[off];
                re[r] = g_e[off];
            }
        }
        const int n0 = nb + t * 32;
#pragma unroll
        for (int r = 0; r < 4; r++) {
            int nn = ty + r * 8;
            float xv = (sx[cur][tx][nn] - mn) * sc;
            int j = min(max(__float2int_rd(xv * 19.0f), 0), NSEG - 1);
            float y = fmaf(xv, ssl[tx][j], ssb[tx][j]);
            out[(size_t)(n0 + nn) * C_CH + c0 + tx] = fmaf(se[cur][tx][nn], eA, y + eB);
        }
        if (t < 3) {
            __syncthreads();
            const int nxt = (t + 1) & 1;
#pragma unroll
            for (int r = 0; r < 4; r++) {
                int cl = ty + r * 8;
                sx[nxt][cl][tx] = rx[r];
                se[nxt][cl][tx] = re[r];
            }
            __syncthreads();
        }
    }
}

// ---------------- launch ----------------
extern "C" void kernel_launch(void* const* d_in, const int* in_sizes, int n_in,
                              void* d_out, int out_size) {
    const float* zf  = (const float*)d_in[0];
    const float* zx  = (const float*)d_in[1];
    const float* ze  = (const float*)d_in[2];
    const float* Wx1 = (const float*)d_in[3];
    const float* bx1 = (const float*)d_in[4];
    const float* Wx2 = (const float*)d_in[5];
    const float* bx2 = (const float*)d_in[6];
    const float* We1 = (const float*)d_in[7];
    const float* be1 = (const float*)d_in[8];
    const float* We2 = (const float*)d_in[9];
    const float* be2 = (const float*)d_in[10];
    const float* Wf1 = (const float*)d_in[11];
    const float* bf1 = (const float*)d_in[12];
    const float* Wf2 = (const float*)d_in[13];
    const float* bf2 = (const float*)d_in[14];
    const void*  dirs = d_in[15];
    float* out = (float*)d_out;

    gen_pwl_kernel<<<1, 128>>>(zf, Wf1, bf1, Wf2, bf2, dirs);
    pass_x_kernel<<<dim3(16, 128), 256>>>(zx, Wx1, bx1, Wx2, bx2);
    pass_e_kernel<<<dim3(16, 128), 256>>>(ze, We1, be1, We2, be2);
    out_kernel<<<dim3(N_PTS / 128, C_CH / 32), dim3(32, 8)>>>(out);
}

// round 14
// speedup vs baseline: 2.5218x; 2.5218x over previous
#include <cuda_runtime.h>
#include <cuda_bf16.h>
#include <math.h>
#include <stdint.h>

#define C_CH   128
#define N_PTS  32768
#define K_PWL  20
#define LATENT 8
#define HID    8
#define NSEG   (K_PWL - 1)

// ---------------- scratch (static device memory; no allocations) ----------------
__device__ float g_x[(size_t)C_CH * N_PTS];     // raw x MLP outputs [C][N]
__device__ float g_e[(size_t)C_CH * N_PTS];     // raw e MLP outputs [C][N]
__device__ float g_slope[C_CH * NSEG];          // per-channel PWL segment slopes
__device__ float g_icept[C_CH * NSEG];          // per-channel PWL segment intercepts
__device__ unsigned int g_minbits[C_CH];
__device__ unsigned int g_maxbits[C_CH];
__device__ float g_minv[C_CH];
__device__ float g_scale[C_CH];
__device__ float g_psum[2048];
__device__ float g_psumsq[2048];
__device__ float g_eA;   // 0.1 * invstd
__device__ float g_eB;   // -0.1 * mean * invstd
__device__ unsigned int g_done;  // zero-init; reset by finalize each run

// xp = linspace(0,1,20) in f32
#define XPV(k) ((float)((double)(k) / 19.0))
__constant__ float c_xp[K_PWL] = {
    XPV(0), XPV(1), XPV(2), XPV(3), XPV(4), XPV(5), XPV(6), XPV(7), XPV(8), XPV(9),
    XPV(10), XPV(11), XPV(12), XPV(13), XPV(14), XPV(15), XPV(16), XPV(17), XPV(18), XPV(19)
};

// ---------------- helpers ----------------
__device__ __forceinline__ unsigned int fenc(float f) {
    unsigned int u = __float_as_uint(f);
    return (u >> 31) ? ~u : (u | 0x80000000u);
}
__device__ __forceinline__ float fdec(unsigned int u) {
    return (u & 0x80000000u) ? __uint_as_float(u & 0x7FFFFFFFu) : __uint_as_float(~u);
}

// Clamped fast tanh (gen kernel only; off the hot path).
__device__ __forceinline__ float tanh_fast(float x) {
    x = fminf(fmaxf(x, -30.0f), 30.0f);
    float t = __expf(2.0f * x);
    return __fdividef(t - 1.0f, t + 1.0f);
}

// Lean 5-instruction tanh for the pass kernels: t = 2^(x*2*log2 e);
// (t-1)/(t+1) = t*r - r with r = rcp(t+1). Inputs bounded (|x| < ~20 given
// N(0,1) inputs and 0.5-scaled weights), no clamp needed (ex2 overflows at x>44).
// Validated in round 13: rel_err 3.4e-7.
__device__ __forceinline__ float tanh5(float x) {
    float t;
    asm("ex2.approx.f32 %0, %1;" : "=f"(t) : "f"(x * 2.8853900817779268f));
    float r;
    asm("rcp.approx.f32 %0, %1;" : "=f"(r) : "f"(t + 1.0f));
    return fmaf(t, r, -r);
}

// ---------------- K1: PWL generator (tiny) + slope/intercept tables + init ----------------
__global__ void gen_pwl_kernel(const float* __restrict__ zf,
                               const float* __restrict__ Wf1, const float* __restrict__ bf1,
                               const float* __restrict__ Wf2, const float* __restrict__ bf2,
                               const void* __restrict__ dirs_raw) {
    int c = threadIdx.x;  // 128 threads, one per channel
    // Parallel dtype detection for `directions`:
    //   bit0 -> some byte at offset %4 != 0 is nonzero  (NOT int32 0/1)
    //   bit1 -> some byte value > 1                     (NOT a 0/1 byte array)
    __shared__ unsigned int flags;
    if (c == 0) { flags = 0u; g_done = 0u; }
    __syncthreads();
    {
        unsigned char v = ((const unsigned char*)dirs_raw)[c];
        unsigned int f = 0u;
        if ((c & 3) != 0 && v != 0) f |= 1u;
        if (v > 1) f |= 2u;
        if (f) atomicOr(&flags, f);
    }
    __syncthreads();
    // mode: 0 = int32, 1 = uint8/bool, 2 = float32
    const int mode = (!(flags & 1u)) ? 0 : ((!(flags & 2u)) ? 1 : 2);

    float z[LATENT];
#pragma unroll
    for (int i = 0; i < LATENT; i++) z[i] = zf[c * LATENT + i];

    float h[HID];
#pragma unroll
    for (int j = 0; j < HID; j++) h[j] = bf1[j];
#pragma unroll
    for (int i = 0; i < LATENT; i++)
#pragma unroll
        for (int j = 0; j < HID; j++) h[j] = fmaf(z[i], Wf1[i * HID + j], h[j]);
#pragma unroll
    for (int j = 0; j < HID; j++) h[j] = tanh_fast(h[j]);

    float pts[K_PWL];
#pragma unroll
    for (int k = 0; k < K_PWL; k++) {
        float s = bf2[k];
#pragma unroll
        for (int j = 0; j < HID; j++) s = fmaf(h[j], Wf2[j * K_PWL + k], s);
        pts[k] = tanh_fast(s);
    }
    // insertion sort ascending
    for (int a = 1; a < K_PWL; a++) {
        float v = pts[a];
        int b = a - 1;
        while (b >= 0 && pts[b] > v) { pts[b + 1] = pts[b]; b--; }
        pts[b + 1] = v;
    }
    bool dir;
    if (mode == 0)      dir = ((const int*)dirs_raw)[c] != 0;
    else if (mode == 1) dir = ((const unsigned char*)dirs_raw)[c] != 0;
    else                dir = ((const float*)dirs_raw)[c] > 0.5f;

    // Per-segment slope/intercept: y(xv) = sl*xv + ic on [xp[k], xp[k+1]]
    for (int k = 0; k < NSEG; k++) {
        float y0 = dir ? pts[k]     : pts[K_PWL - 1 - k];
        float y1 = dir ? pts[k + 1] : pts[K_PWL - 2 - k];
        float sl = (y1 - y0) / (c_xp[k + 1] - c_xp[k] + 1e-7f);
        g_slope[c * NSEG + k] = sl;
        g_icept[c * NSEG + k] = fmaf(-c_xp[k], sl, y0);
    }

    g_minbits[c] = 0xFFFFFFFFu;
    g_maxbits[c] = 0u;
}

// ---------------- K2: x MLP + per-channel min/max ----------------
__global__ void __launch_bounds__(256) pass_x_kernel(
    const float* __restrict__ zx,
    const float* __restrict__ W1, const float* __restrict__ b1,
    const float* __restrict__ W2, const float* __restrict__ b2) {
    float W1r[64];
#pragma unroll
    for (int i = 0; i < 64; i++) W1r[i] = __ldg(W1 + i);
    float b1r[HID], W2r[HID];
#pragma unroll
    for (int j = 0; j < HID; j++) { b1r[j] = __ldg(b1 + j); W2r[j] = __ldg(W2 + j); }
    float b2r = __ldg(b2);

    const int c = blockIdx.y;
    const int tid = threadIdx.x;
    const size_t base = (size_t)c * N_PTS;
    const int n0 = blockIdx.x * 2048;

    float lmin = 1e30f, lmax = -1e30f;
#pragma unroll
    for (int k = 0; k < 8; k++) {
        int n = n0 + k * 256 + tid;
        const float4* p = reinterpret_cast<const float4*>(zx + (base + n) * LATENT);
        float4 a = p[0], bq = p[1];
        float z[8] = {a.x, a.y, a.z, a.w, bq.x, bq.y, bq.z, bq.w};
        float h[HID];
#pragma unroll
        for (int j = 0; j < HID; j++) h[j] = b1r[j];
#pragma unroll
        for (int i = 0; i < LATENT; i++)
#pragma unroll
            for (int j = 0; j < HID; j++) h[j] = fmaf(z[i], W1r[i * HID + j], h[j]);
        float o = b2r;
#pragma unroll
        for (int j = 0; j < HID; j++) o = fmaf(tanh5(h[j]), W2r[j], o);
        float xv = tanh5(o);
        g_x[base + n] = xv;
        lmin = fminf(lmin, xv);
        lmax = fmaxf(lmax, xv);
    }

    __shared__ float red[256];
    red[tid] = lmin; __syncthreads();
    for (int s = 128; s; s >>= 1) { if (tid < s) red[tid] = fminf(red[tid], red[tid + s]); __syncthreads(); }
    if (tid == 0) atomicMin(&g_minbits[c], fenc(red[0]));
    __syncthreads();
    red[tid] = lmax; __syncthreads();
    for (int s = 128; s; s >>= 1) { if (tid < s) red[tid] = fmaxf(red[tid], red[tid + s]); __syncthreads(); }
    if (tid == 0) atomicMax(&g_maxbits[c], fenc(red[0]));
}

// ---------------- K3: e MLP + global sum/sumsq partials + last-block finalize ----------------
__global__ void __launch_bounds__(256) pass_e_kernel(
    const float* __restrict__ ze,
    const float* __restrict__ W1, const float* __restrict__ b1,
    const float* __restrict__ W2, const float* __restrict__ b2) {
    float W1r[64];
#pragma unroll
    for (int i = 0; i < 64; i++) W1r[i] = __ldg(W1 + i);
    float b1r[HID], W2r[HID];
#pragma unroll
    for (int j = 0; j < HID; j++) { b1r[j] = __ldg(b1 + j); W2r[j] = __ldg(W2 + j); }
    float b2r = __ldg(b2);

    const int c = blockIdx.y;
    const int tid = threadIdx.x;
    const size_t base = (size_t)c * N_PTS;
    const int n0 = blockIdx.x * 2048;

    float ls = 0.0f, lq = 0.0f;
#pragma unroll
    for (int k = 0; k < 8; k++) {
        int n = n0 + k * 256 + tid;
        const float4* p = reinterpret_cast<const float4*>(ze + (base + n) * LATENT);
        float4 a = p[0], bq = p[1];
        float z[8] = {a.x, a.y, a.z, a.w, bq.x, bq.y, bq.z, bq.w};
        float h[HID];
#pragma unroll
        for (int j = 0; j < HID; j++) h[j] = b1r[j];
#pragma unroll
        for (int i = 0; i < LATENT; i++)
#pragma unroll
            for (int j = 0; j < HID; j++) h[j] = fmaf(z[i], W1r[i * HID + j], h[j]);
        float o = b2r;
#pragma unroll
        for (int j = 0; j < HID; j++) o = fmaf(tanh5(h[j]), W2r[j], o);
        float ev = tanh5(o);
        g_e[base + n] = ev;
        ls += ev;
        lq = fmaf(ev, ev, lq);
    }

    __shared__ float reds[256];
    __shared__ float redq[256];
    __shared__ bool amLast;
    reds[tid] = ls; redq[tid] = lq; __syncthreads();
    for (int s = 128; s; s >>= 1) {
        if (tid < s) { reds[tid] += reds[tid + s]; redq[tid] += redq[tid + s]; }
        __syncthreads();
    }
    if (tid == 0) {
        int pid = blockIdx.y * gridDim.x + blockIdx.x;
        g_psum[pid] = reds[0];
        g_psumsq[pid] = redq[0];
        __threadfence();                       // release partials
        unsigned int t = atomicAdd(&g_done, 1u);
        amLast = (t == 2048u - 1u);
    }
    __syncthreads();

    // Last block performs the deterministic fixed-order fp64 reduce.
    if (amLast) {
        __threadfence();                       // acquire all partials
        __shared__ double sds[256];
        double s = 0.0, q = 0.0;
#pragma unroll
        for (int i = 0; i < 8; i++) {
            int idx = tid + i * 256;
            s += (double)g_psum[idx];
            q += (double)g_psumsq[idx];
        }
        sds[tid] = s; __syncthreads();
        for (int k = 128; k; k >>= 1) {
            if (tid < k) sds[tid] += sds[tid + k];
            __syncthreads();
        }
        double stot = sds[0]; __syncthreads();
        sds[tid] = q; __syncthreads();
        for (int k = 128; k; k >>= 1) {
            if (tid < k) sds[tid] += sds[tid + k];
            __syncthreads();
        }
        double qtot = sds[0];
        if (tid == 0) {
            double CN = (double)C_CH * (double)N_PTS;
            double mean = stot / CN;
            double var = (qtot - stot * stot / CN) / (CN - 1.0);
            double invstd = 1.0 / sqrt(var);
            g_eA = (float)(0.1 * invstd);
            g_eB = (float)(-0.1 * mean * invstd);
            g_done = 0u;                       // reset for next graph replay
        }
        if (tid < C_CH) {
            float mn = fdec(g_minbits[tid]);   // pass_x completed before this kernel (stream order)
            float mx = fdec(g_maxbits[tid]);
            g_minv[tid] = mn;
            g_scale[tid] = 1.0f / (mx - mn);
        }
        __threadfence();
    }
}

// ---------------- K4: transpose + direct-index PWL + noise (double-buffered) ----------------
// Block covers 32 channels x 128 n (4 sub-tiles of 32x32, pipelined).
__global__ void __launch_bounds__(256) out_kernel(float* __restrict__ out) {
    __shared__ float sx[2][32][33];
    __shared__ float se[2][32][33];
    __shared__ float ssl[32][NSEG + 1];
    __shared__ float ssb[32][NSEG + 1];
    __shared__ float smn[32];
    __shared__ float ssc[32];

    const int tx = threadIdx.x, ty = threadIdx.y;
    const int tid = ty * 32 + tx;
    const int nb = blockIdx.x * 128;
    const int c0 = blockIdx.y * 32;

    for (int idx = tid; idx < 32 * NSEG; idx += 256) {
        int cl = idx / NSEG, k = idx % NSEG;
        ssl[cl][k] = g_slope[(c0 + cl) * NSEG + k];
        ssb[cl][k] = g_icept[(c0 + cl) * NSEG + k];
    }
    if (tid < 32) {
        smn[tid] = g_minv[c0 + tid];
        ssc[tid] = g_scale[c0 + tid];
    }
    const float eA = g_eA, eB = g_eB;

    // Preload tile 0
    float rx[4], re[4];
#pragma unroll
    for (int r = 0; r < 4; r++) {
        int cl = ty + r * 8;
        size_t off = (size_t)(c0 + cl) * N_PTS + nb + tx;
        rx[r] = g_x[off];
        re[r] = g_e[off];
    }
#pragma unroll
    for (int r = 0; r < 4; r++) {
        int cl = ty + r * 8;
        sx[0][cl][tx] = rx[r];
        se[0][cl][tx] = re[r];
    }
    __syncthreads();

    const float mn = smn[tx], sc = ssc[tx];

#pragma unroll
    for (int t = 0; t < 4; t++) {
        const int cur = t & 1;
        // Issue next tile's loads (latency overlaps compute below)
        if (t < 3) {
            const int n1 = nb + (t + 1) * 32;
#pragma unroll
            for (int r = 0; r < 4; r++) {
                int cl = ty + r * 8;
                size_t off = (size_t)(c0 + cl) * N_PTS + n1 + tx;
                rx[r] = g_x[off];
                re[r] = g_e[off];
            }
        }
        // Compute current tile from smem
        const int n0 = nb + t * 32;
#pragma unroll
        for (int r = 0; r < 4; r++) {
            int nn = ty + r * 8;
            float xv = (sx[cur][tx][nn] - mn) * sc;
            int j = min(max(__float2int_rd(xv * 19.0f), 0), NSEG - 1);
            float y = fmaf(xv, ssl[tx][j], ssb[tx][j]);
            out[(size_t)(n0 + nn) * C_CH + c0 + tx] = fmaf(se[cur][tx][nn], eA, y + eB);
        }
        if (t < 3) {
            __syncthreads();
            const int nxt = (t + 1) & 1;
#pragma unroll
            for (int r = 0; r < 4; r++) {
                int cl = ty + r * 8;
                sx[nxt][cl][tx] = rx[r];
                se[nxt][cl][tx] = re[r];
            }
            __syncthreads();
        }
    }
}

// ---------------- launch ----------------
extern "C" void kernel_launch(void* const* d_in, const int* in_sizes, int n_in,
                              void* d_out, int out_size) {
    const float* zf  = (const float*)d_in[0];
    const float* zx  = (const float*)d_in[1];
    const float* ze  = (const float*)d_in[2];
    const float* Wx1 = (const float*)d_in[3];
    const float* bx1 = (const float*)d_in[4];
    const float* Wx2 = (const float*)d_in[5];
    const float* bx2 = (const float*)d_in[6];
    const float* We1 = (const float*)d_in[7];
    const float* be1 = (const float*)d_in[8];
    const float* We2 = (const float*)d_in[9];
    const float* be2 = (const float*)d_in[10];
    const float* Wf1 = (const float*)d_in[11];
    const float* bf1 = (const float*)d_in[12];
    const float* Wf2 = (const float*)d_in[13];
    const float* bf2 = (const float*)d_in[14];
    const void*  dirs = d_in[15];
    float* out = (float*)d_out;

    gen_pwl_kernel<<<1, 128>>>(zf, Wf1, bf1, Wf2, bf2, dirs);
    pass_x_kernel<<<dim3(16, 128), 256>>>(zx, Wx1, bx1, Wx2, bx2);
    pass_e_kernel<<<dim3(16, 128), 256>>>(ze, We1, be1, We2, be2);
    out_kernel<<<dim3(N_PTS / 128, C_CH / 32), dim3(32, 8)>>>(out);
}

// round 15
// speedup vs baseline: 2.5889x; 1.0266x over previous
#include <cuda_runtime.h>
#include <cuda_bf16.h>
#include <math.h>
#include <stdint.h>

#define C_CH   128
#define N_PTS  32768
#define K_PWL  20
#define LATENT 8
#define HID    8
#define NSEG   (K_PWL - 1)

// ---------------- scratch (static device memory; no allocations) ----------------
// x/e stored as int16 fixed-point: q = round(v * 32767), |v| <= 1 (tanh output).
// Halves scratch traffic (64MB -> 32MB round trip). Quantization err 3.1e-5.
__device__ short g_xq[(size_t)C_CH * N_PTS];
__device__ short g_eq[(size_t)C_CH * N_PTS];
__device__ float g_slope[C_CH * NSEG];          // per-channel PWL segment slopes
__device__ float g_icept[C_CH * NSEG];          // per-channel PWL segment intercepts
__device__ int   g_min_q[C_CH];                 // per-channel min of quantized x
__device__ int   g_max_q[C_CH];
__device__ float g_minv[C_CH];                  // (float)min_q
__device__ float g_scale[C_CH];                 // 1/(float)(max_q - min_q)  [k cancels]
__device__ float g_psum[2048];
__device__ float g_psumsq[2048];
__device__ float g_eA;   // 0.1 * invstd * (1/32767)  [decode folded in]
__device__ float g_eB;   // -0.1 * mean * invstd
__device__ unsigned int g_done;  // zero-init; reset by finalize each run

#define QSCALE 32767.0f
#define QINV   (1.0f / 32767.0f)

// xp = linspace(0,1,20) in f32
#define XPV(k) ((float)((double)(k) / 19.0))
__constant__ float c_xp[K_PWL] = {
    XPV(0), XPV(1), XPV(2), XPV(3), XPV(4), XPV(5), XPV(6), XPV(7), XPV(8), XPV(9),
    XPV(10), XPV(11), XPV(12), XPV(13), XPV(14), XPV(15), XPV(16), XPV(17), XPV(18), XPV(19)
};

// ---------------- helpers ----------------
// Clamped fast tanh (gen kernel only; off the hot path).
__device__ __forceinline__ float tanh_fast(float x) {
    x = fminf(fmaxf(x, -30.0f), 30.0f);
    float t = __expf(2.0f * x);
    return __fdividef(t - 1.0f, t + 1.0f);
}

// Lean 5-instruction tanh (validated: rel_err 3.4e-7 in rounds 13/14).
__device__ __forceinline__ float tanh5(float x) {
    float t;
    asm("ex2.approx.f32 %0, %1;" : "=f"(t) : "f"(x * 2.8853900817779268f));
    float r;
    asm("rcp.approx.f32 %0, %1;" : "=f"(r) : "f"(t + 1.0f));
    return fmaf(t, r, -r);
}

// ---------------- K1: PWL generator (tiny) + slope/intercept tables + init ----------------
__global__ void gen_pwl_kernel(const float* __restrict__ zf,
                               const float* __restrict__ Wf1, const float* __restrict__ bf1,
                               const float* __restrict__ Wf2, const float* __restrict__ bf2,
                               const void* __restrict__ dirs_raw) {
    int c = threadIdx.x;  // 128 threads, one per channel
    // Parallel dtype detection for `directions`:
    //   bit0 -> some byte at offset %4 != 0 is nonzero  (NOT int32 0/1)
    //   bit1 -> some byte value > 1                     (NOT a 0/1 byte array)
    __shared__ unsigned int flags;
    if (c == 0) { flags = 0u; g_done = 0u; }
    __syncthreads();
    {
        unsigned char v = ((const unsigned char*)dirs_raw)[c];
        unsigned int f = 0u;
        if ((c & 3) != 0 && v != 0) f |= 1u;
        if (v > 1) f |= 2u;
        if (f) atomicOr(&flags, f);
    }
    __syncthreads();
    // mode: 0 = int32, 1 = uint8/bool, 2 = float32
    const int mode = (!(flags & 1u)) ? 0 : ((!(flags & 2u)) ? 1 : 2);

    float z[LATENT];
#pragma unroll
    for (int i = 0; i < LATENT; i++) z[i] = zf[c * LATENT + i];

    float h[HID];
#pragma unroll
    for (int j = 0; j < HID; j++) h[j] = bf1[j];
#pragma unroll
    for (int i = 0; i < LATENT; i++)
#pragma unroll
        for (int j = 0; j < HID; j++) h[j] = fmaf(z[i], Wf1[i * HID + j], h[j]);
#pragma unroll
    for (int j = 0; j < HID; j++) h[j] = tanh_fast(h[j]);

    float pts[K_PWL];
#pragma unroll
    for (int k = 0; k < K_PWL; k++) {
        float s = bf2[k];
#pragma unroll
        for (int j = 0; j < HID; j++) s = fmaf(h[j], Wf2[j * K_PWL + k], s);
        pts[k] = tanh_fast(s);
    }
    // insertion sort ascending
    for (int a = 1; a < K_PWL; a++) {
        float v = pts[a];
        int b = a - 1;
        while (b >= 0 && pts[b] > v) { pts[b + 1] = pts[b]; b--; }
        pts[b + 1] = v;
    }
    bool dir;
    if (mode == 0)      dir = ((const int*)dirs_raw)[c] != 0;
    else if (mode == 1) dir = ((const unsigned char*)dirs_raw)[c] != 0;
    else                dir = ((const float*)dirs_raw)[c] > 0.5f;

    // Per-segment slope/intercept: y(xv) = sl*xv + ic on [xp[k], xp[k+1]]
    for (int k = 0; k < NSEG; k++) {
        float y0 = dir ? pts[k]     : pts[K_PWL - 1 - k];
        float y1 = dir ? pts[k + 1] : pts[K_PWL - 2 - k];
        float sl = (y1 - y0) / (c_xp[k + 1] - c_xp[k] + 1e-7f);
        g_slope[c * NSEG + k] = sl;
        g_icept[c * NSEG + k] = fmaf(-c_xp[k], sl, y0);
    }

    g_min_q[c] = 0x7FFFFFFF;
    g_max_q[c] = (int)0x80000000;
}

// ---------------- K2: x MLP + per-channel min/max (int16 scratch) ----------------
__global__ void __launch_bounds__(256) pass_x_kernel(
    const float* __restrict__ zx,
    const float* __restrict__ W1, const float* __restrict__ b1,
    const float* __restrict__ W2, const float* __restrict__ b2) {
    float W1r[64];
#pragma unroll
    for (int i = 0; i < 64; i++) W1r[i] = __ldg(W1 + i);
    float b1r[HID], W2r[HID];
#pragma unroll
    for (int j = 0; j < HID; j++) { b1r[j] = __ldg(b1 + j); W2r[j] = __ldg(W2 + j); }
    float b2r = __ldg(b2);

    const int c = blockIdx.y;
    const int tid = threadIdx.x;
    const size_t base = (size_t)c * N_PTS;
    const int n0 = blockIdx.x * 2048;

    int lmin = 0x7FFFFFFF, lmax = (int)0x80000000;
#pragma unroll
    for (int k = 0; k < 8; k++) {
        int n = n0 + k * 256 + tid;
        const float4* p = reinterpret_cast<const float4*>(zx + (base + n) * LATENT);
        float4 a = p[0], bq = p[1];
        float z[8] = {a.x, a.y, a.z, a.w, bq.x, bq.y, bq.z, bq.w};
        float h[HID];
#pragma unroll
        for (int j = 0; j < HID; j++) h[j] = b1r[j];
#pragma unroll
        for (int i = 0; i < LATENT; i++)
#pragma unroll
            for (int j = 0; j < HID; j++) h[j] = fmaf(z[i], W1r[i * HID + j], h[j]);
        float o = b2r;
#pragma unroll
        for (int j = 0; j < HID; j++) o = fmaf(tanh5(h[j]), W2r[j], o);
        float xv = tanh5(o);
        int q = __float2int_rn(xv * QSCALE);
        g_xq[base + n] = (short)q;
        lmin = min(lmin, q);
        lmax = max(lmax, q);
    }

    __shared__ int red1[256];
    __shared__ int red2[256];
    red1[tid] = lmin; red2[tid] = lmax; __syncthreads();
    for (int s = 128; s; s >>= 1) {
        if (tid < s) {
            red1[tid] = min(red1[tid], red1[tid + s]);
            red2[tid] = max(red2[tid], red2[tid + s]);
        }
        __syncthreads();
    }
    if (tid == 0) {
        atomicMin(&g_min_q[c], red1[0]);
        atomicMax(&g_max_q[c], red2[0]);
    }
}

// ---------------- K3: e MLP + global sum/sumsq partials + last-block finalize ----------------
__global__ void __launch_bounds__(256) pass_e_kernel(
    const float* __restrict__ ze,
    const float* __restrict__ W1, const float* __restrict__ b1,
    const float* __restrict__ W2, const float* __restrict__ b2) {
    float W1r[64];
#pragma unroll
    for (int i = 0; i < 64; i++) W1r[i] = __ldg(W1 + i);
    float b1r[HID], W2r[HID];
#pragma unroll
    for (int j = 0; j < HID; j++) { b1r[j] = __ldg(b1 + j); W2r[j] = __ldg(W2 + j); }
    float b2r = __ldg(b2);

    const int c = blockIdx.y;
    const int tid = threadIdx.x;
    const size_t base = (size_t)c * N_PTS;
    const int n0 = blockIdx.x * 2048;

    float ls = 0.0f, lq = 0.0f;
#pragma unroll
    for (int k = 0; k < 8; k++) {
        int n = n0 + k * 256 + tid;
        const float4* p = reinterpret_cast<const float4*>(ze + (base + n) * LATENT);
        float4 a = p[0], bq = p[1];
        float z[8] = {a.x, a.y, a.z, a.w, bq.x, bq.y, bq.z, bq.w};
        float h[HID];
#pragma unroll
        for (int j = 0; j < HID; j++) h[j] = b1r[j];
#pragma unroll
        for (int i = 0; i < LATENT; i++)
#pragma unroll
            for (int j = 0; j < HID; j++) h[j] = fmaf(z[i], W1r[i * HID + j], h[j]);
        float o = b2r;
#pragma unroll
        for (int j = 0; j < HID; j++) o = fmaf(tanh5(h[j]), W2r[j], o);
        float ev = tanh5(o);
        int q = __float2int_rn(ev * QSCALE);
        g_eq[base + n] = (short)q;
        // stats on the DECODED value so mean/std match what out_kernel reads
        float evd = (float)q * QINV;
        ls += evd;
        lq = fmaf(evd, evd, lq);
    }

    __shared__ float reds[256];
    __shared__ float redq[256];
    __shared__ bool amLast;
    reds[tid] = ls; redq[tid] = lq; __syncthreads();
    for (int s = 128; s; s >>= 1) {
        if (tid < s) { reds[tid] += reds[tid + s]; redq[tid] += redq[tid + s]; }
        __syncthreads();
    }
    if (tid == 0) {
        int pid = blockIdx.y * gridDim.x + blockIdx.x;
        g_psum[pid] = reds[0];
        g_psumsq[pid] = redq[0];
        __threadfence();                       // release partials
        unsigned int t = atomicAdd(&g_done, 1u);
        amLast = (t == 2048u - 1u);
    }
    __syncthreads();

    // Last block performs the deterministic fixed-order fp64 reduce.
    if (amLast) {
        __threadfence();                       // acquire all partials
        __shared__ double sds[256];
        double s = 0.0, q = 0.0;
#pragma unroll
        for (int i = 0; i < 8; i++) {
            int idx = tid + i * 256;
            s += (double)g_psum[idx];
            q += (double)g_psumsq[idx];
        }
        sds[tid] = s; __syncthreads();
        for (int k = 128; k; k >>= 1) {
            if (tid < k) sds[tid] += sds[tid + k];
            __syncthreads();
        }
        double stot = sds[0]; __syncthreads();
        sds[tid] = q; __syncthreads();
        for (int k = 128; k; k >>= 1) {
            if (tid < k) sds[tid] += sds[tid + k];
            __syncthreads();
        }
        double qtot = sds[0];
        if (tid == 0) {
            double CN = (double)C_CH * (double)N_PTS;
            double mean = stot / CN;
            double var = (qtot - stot * stot / CN) / (CN - 1.0);
            double invstd = 1.0 / sqrt(var);
            g_eA = (float)(0.1 * invstd * (double)QINV);  // decode folded in
            g_eB = (float)(-0.1 * mean * invstd);
            g_done = 0u;                       // reset for next graph replay
        }
        if (tid < C_CH) {
            int mn = g_min_q[tid];             // pass_x completed before this kernel (stream order)
            int mx = g_max_q[tid];
            g_minv[tid] = (float)mn;
            // xv = (q - mn)/(mx - mn): quantization scale k cancels exactly
            g_scale[tid] = 1.0f / (float)(mx - mn);
        }
        __threadfence();
    }
}

// ---------------- K4: transpose + direct-index PWL + noise (double-buffered) ----------------
// Block covers 32 channels x 128 n (4 sub-tiles of 32x32, pipelined).
__global__ void __launch_bounds__(256) out_kernel(float* __restrict__ out) {
    __shared__ float sx[2][32][33];
    __shared__ float se[2][32][33];
    __shared__ float ssl[32][NSEG + 1];
    __shared__ float ssb[32][NSEG + 1];
    __shared__ float smn[32];
    __shared__ float ssc[32];

    const int tx = threadIdx.x, ty = threadIdx.y;
    const int tid = ty * 32 + tx;
    const int nb = blockIdx.x * 128;
    const int c0 = blockIdx.y * 32;

    for (int idx = tid; idx < 32 * NSEG; idx += 256) {
        int cl = idx / NSEG, k = idx % NSEG;
        ssl[cl][k] = g_slope[(c0 + cl) * NSEG + k];
        ssb[cl][k] = g_icept[(c0 + cl) * NSEG + k];
    }
    if (tid < 32) {
        smn[tid] = g_minv[c0 + tid];
        ssc[tid] = g_scale[c0 + tid];
    }
    const float eA = g_eA, eB = g_eB;

    // Preload tile 0 (decode int16 -> float at load time)
    float rx[4], re[4];
#pragma unroll
    for (int r = 0; r < 4; r++) {
        int cl = ty + r * 8;
        size_t off = (size_t)(c0 + cl) * N_PTS + nb + tx;
        rx[r] = (float)g_xq[off];
        re[r] = (float)g_eq[off];
    }
#pragma unroll
    for (int r = 0; r < 4; r++) {
        int cl = ty + r * 8;
        sx[0][cl][tx] = rx[r];
        se[0][cl][tx] = re[r];
    }
    __syncthreads();

    const float mn = smn[tx], sc = ssc[tx];

#pragma unroll
    for (int t = 0; t < 4; t++) {
        const int cur = t & 1;
        // Issue next tile's loads (latency overlaps compute below)
        if (t < 3) {
            const int n1 = nb + (t + 1) * 32;
#pragma unroll
            for (int r = 0; r < 4; r++) {
                int cl = ty + r * 8;
                size_t off = (size_t)(c0 + cl) * N_PTS + n1 + tx;
                rx[r] = (float)g_xq[off];
                re[r] = (float)g_eq[off];
            }
        }
        // Compute current tile from smem
        const int n0 = nb + t * 32;
#pragma unroll
        for (int r = 0; r < 4; r++) {
            int nn = ty + r * 8;
            float xv = (sx[cur][tx][nn] - mn) * sc;   // k cancels: pure int-space normalize
            int j = min(max(__float2int_rd(xv * 19.0f), 0), NSEG - 1);
            float y = fmaf(xv, ssl[tx][j], ssb[tx][j]);
            out[(size_t)(n0 + nn) * C_CH + c0 + tx] = fmaf(se[cur][tx][nn], eA, y + eB);
        }
        if (t < 3) {
            __syncthreads();
            const int nxt = (t + 1) & 1;
#pragma unroll
            for (int r = 0; r < 4; r++) {
                int cl = ty + r * 8;
                sx[nxt][cl][tx] = rx[r];
                se[nxt][cl][tx] = re[r];
            }
            __syncthreads();
        }
    }
}

// ---------------- launch ----------------
extern "C" void kernel_launch(void* const* d_in, const int* in_sizes, int n_in,
                              void* d_out, int out_size) {
    const float* zf  = (const float*)d_in[0];
    const float* zx  = (const float*)d_in[1];
    const float* ze  = (const float*)d_in[2];
    const float* Wx1 = (const float*)d_in[3];
    const float* bx1 = (const float*)d_in[4];
    const float* Wx2 = (const float*)d_in[5];
    const float* bx2 = (const float*)d_in[6];
    const float* We1 = (const float*)d_in[7];
    const float* be1 = (const float*)d_in[8];
    const float* We2 = (const float*)d_in[9];
    const float* be2 = (const float*)d_in[10];
    const float* Wf1 = (const float*)d_in[11];
    const float* bf1 = (const float*)d_in[12];
    const float* Wf2 = (const float*)d_in[13];
    const float* bf2 = (const float*)d_in[14];
    const void*  dirs = d_in[15];
    float* out = (float*)d_out;

    gen_pwl_kernel<<<1, 128>>>(zf, Wf1, bf1, Wf2, bf2, dirs);
    pass_x_kernel<<<dim3(16, 128), 256>>>(zx, Wx1, bx1, Wx2, bx2);
    pass_e_kernel<<<dim3(16, 128), 256>>>(ze, We1, be1, We2, be2);
    out_kernel<<<dim3(N_PTS / 128, C_CH / 32), dim3(32, 8)>>>(out);
}